// round 6
// baseline (speedup 1.0000x reference)
#include <cuda_runtime.h>
#include <cstdint>

#define NROWS 32768
#define KCODES 8192
#define DD 256
#define QSIZE (NROWS * DD)

#define TM 128
#define NSEG 2048
#define NUNITS ((NROWS / TM) * (KCODES / NSEG))   // 1024
#define NTPU (NSEG / 128)                         // 16 tiles of 128 codes
#define CAP 64
#define DELTA 3e-3f

// smem byte offsets
#define SM_A   0
#define SM_B0  32768
#define SM_B1  65536
#define SM_ZZ  98304
#define SM_SZ  98816
#define SM_EE  99328
#define SM_SEC 99840
#define SM_BD  100352
#define SM_TOTAL 100864

// ---- device scratch ----
__device__ int      g_bestk[NROWS];
__device__ float    g_zz[NROWS];
__device__ float    g_ee[KCODES];
__device__ float    g_szr[NROWS];
__device__ float    g_sec[KCODES];
__device__ float    g_partial[8192];
__device__ int      g_work;
__device__ int      g_ncand[NROWS];
__device__ int      g_cand[NROWS * CAP];
__device__ uint32_t g_zqT[NROWS * 64];    // [row>>7][k4][row&127]
__device__ uint32_t g_eqT[KCODES * 64];   // [code>>7][k4][code&127]

__device__ __forceinline__ uint32_t smem_u32(const void* p) {
    uint32_t a;
    asm("{ .reg .u64 t; cvta.to.shared.u64 t, %1; cvt.u32.u64 %0, t; }" : "=r"(a) : "l"(p));
    return a;
}
// signed dp4a (explicit: packed s8x4 dot-product into s32 accumulator)
__device__ __forceinline__ int dp4a_s32(uint32_t a, uint32_t b, int c) {
    int r;
    asm("dp4a.s32.s32 %0, %1, %2, %3;" : "=r"(r) : "r"(a), "r"(b), "r"(c));
    return r;
}
#define CPASYNC16(dst, src) \
    asm volatile("cp.async.cg.shared.global [%0], [%1], 16;" :: "r"(dst), "l"(src))
#define CPCOMMIT() asm volatile("cp.async.commit_group;" ::: "memory")
#define CPWAIT1()  asm volatile("cp.async.wait_group 1;" ::: "memory")

// -------- init (graph-replayable) --------
__global__ void vq_init_kernel() {
    int i = blockIdx.x * 256 + threadIdx.x;
    g_ncand[i] = 0;
    if (i == 0) g_work = 0;
}

// -------- exact row squared-norms (matched reference; unchanged) --------
__global__ void vq_norms_kernel(const float* __restrict__ src, float* __restrict__ dst,
                                int nrows) {
    int w = (blockIdx.x * blockDim.x + threadIdx.x) >> 5;
    int lane = threadIdx.x & 31;
    if (w >= nrows) return;
    const float* row = src + (size_t)w * DD;
    float s = 0.f;
#pragma unroll
    for (int j = 0; j < DD / 32; j++) {
        float v = row[lane + 32 * j];
        s = fmaf(v, v, s);
    }
#pragma unroll
    for (int o = 16; o; o >>= 1) s += __shfl_xor_sync(0xffffffffu, s, o);
    if (lane == 0) dst[w] = s;
}

// -------- per-row max-abs int8 quantize, transposed output --------
__global__ void vq_quant_kernel(const float* __restrict__ src, uint32_t* __restrict__ dstT,
                                float* __restrict__ scl, int n) {
    int w = (blockIdx.x * blockDim.x + threadIdx.x) >> 5;
    int lane = threadIdx.x & 31;
    if (w >= n) return;
    const float4* r4 = reinterpret_cast<const float4*>(src + (size_t)w * DD);
    float4 v0 = r4[2 * lane];
    float4 v1 = r4[2 * lane + 1];
    float m = fmaxf(fmaxf(fabsf(v0.x), fabsf(v0.y)), fmaxf(fabsf(v0.z), fabsf(v0.w)));
    m = fmaxf(m, fmaxf(fmaxf(fabsf(v1.x), fabsf(v1.y)), fmaxf(fabsf(v1.z), fabsf(v1.w))));
#pragma unroll
    for (int o = 16; o; o >>= 1) m = fmaxf(m, __shfl_xor_sync(0xffffffffu, m, o));
    m = fmaxf(m, 1e-30f);
    const float inv = 127.0f / m;
    int q0 = max(-127, min(127, __float2int_rn(v0.x * inv)));
    int q1 = max(-127, min(127, __float2int_rn(v0.y * inv)));
    int q2 = max(-127, min(127, __float2int_rn(v0.z * inv)));
    int q3 = max(-127, min(127, __float2int_rn(v0.w * inv)));
    uint32_t w0 = (q0 & 255) | ((q1 & 255) << 8) | ((q2 & 255) << 16) | ((uint32_t)(q3 & 255) << 24);
    q0 = max(-127, min(127, __float2int_rn(v1.x * inv)));
    q1 = max(-127, min(127, __float2int_rn(v1.y * inv)));
    q2 = max(-127, min(127, __float2int_rn(v1.z * inv)));
    q3 = max(-127, min(127, __float2int_rn(v1.w * inv)));
    uint32_t w1 = (q0 & 255) | ((q1 & 255) << 8) | ((q2 & 255) << 16) | ((uint32_t)(q3 & 255) << 24);
    const size_t base = (size_t)(w >> 7) * 8192 + (w & 127);
    dstT[base + (size_t)(2 * lane) * 128] = w0;
    dstT[base + (size_t)(2 * lane + 1) * 128] = w1;
    if (lane == 0) scl[w] = m / 127.0f;
}

// -------- dp4a int8 screening: approx d, running-min candidate collection --------
// 256 thr = 16 tx (codes) x 16 ty (rows). Thread tile 8x8 (2x2 groups of 4x4).
__global__ void __launch_bounds__(256, 1) vq_screen_kernel() {
    extern __shared__ char smem[];
    __shared__ int s_u;
    const uint32_t sbase = smem_u32(smem);
    const uint32_t* Aw = reinterpret_cast<const uint32_t*>(smem + SM_A);
    float* zzs  = reinterpret_cast<float*>(smem + SM_ZZ);
    float* szrs = reinterpret_cast<float*>(smem + SM_SZ);
    float* ees  = reinterpret_cast<float*>(smem + SM_EE);
    float* secs = reinterpret_cast<float*>(smem + SM_SEC);
    unsigned int* bdU = reinterpret_cast<unsigned int*>(smem + SM_BD);

    const int tid = threadIdx.x;
    const int tx = tid & 15;
    const int ty = tid >> 4;

    for (;;) {
        if (tid == 0) s_u = atomicAdd(&g_work, 1);
        __syncthreads();
        const int u = s_u;
        if (u >= NUNITS) return;
        const int rb = u & 255;
        const int cq = u >> 8;
        const int row0 = rb * TM;
        const int code0 = cq * NSEG;

        // group G0: A tile (32KB) + B tile 0 (32KB)
#pragma unroll
        for (int i = 0; i < 8; i++) {
            int f = tid + 256 * i;
            CPASYNC16(sbase + SM_A + f * 16, g_zqT + (size_t)rb * 8192 + f * 4);
        }
#pragma unroll
        for (int i = 0; i < 8; i++) {
            int f = tid + 256 * i;
            CPASYNC16(sbase + SM_B0 + f * 16, g_eqT + (size_t)(cq * 16) * 8192 + f * 4);
        }
        CPCOMMIT();
        if (tid < 128) {
            zzs[tid]  = g_zz[row0 + tid];
            szrs[tid] = g_szr[row0 + tid];
            bdU[tid]  = 0x7f800000u;
        }

        for (int t = 0; t < NTPU; t++) {
            if (tid < 128) {
                ees[tid]  = g_ee[code0 + t * 128 + tid];
                secs[tid] = g_sec[code0 + t * 128 + tid];
            }
            if (t + 1 < NTPU) {
                const uint32_t bb = sbase + (((t + 1) & 1) ? SM_B1 : SM_B0);
                const uint32_t* src = g_eqT + (size_t)(cq * 16 + t + 1) * 8192;
#pragma unroll
                for (int i = 0; i < 8; i++) {
                    int f = tid + 256 * i;
                    CPASYNC16(bb + f * 16, src + f * 4);
                }
            }
            CPCOMMIT();
            CPWAIT1();
            __syncthreads();

            const uint32_t* Bw = reinterpret_cast<const uint32_t*>(
                smem + ((t & 1) ? SM_B1 : SM_B0));

            int acc[2][2][4][4];
#pragma unroll
            for (int p = 0; p < 2; p++)
#pragma unroll
                for (int qg = 0; qg < 2; qg++)
#pragma unroll
                    for (int i = 0; i < 4; i++)
#pragma unroll
                        for (int j = 0; j < 4; j++) acc[p][qg][i][j] = 0;

#pragma unroll 4
            for (int k4 = 0; k4 < 64; k4++) {
                uint4 a0 = *reinterpret_cast<const uint4*>(Aw + k4 * 128 + ty * 4);
                uint4 a1 = *reinterpret_cast<const uint4*>(Aw + k4 * 128 + 64 + ty * 4);
                uint4 b0 = *reinterpret_cast<const uint4*>(Bw + k4 * 128 + tx * 4);
                uint4 b1 = *reinterpret_cast<const uint4*>(Bw + k4 * 128 + 64 + tx * 4);
                const uint32_t av[2][4] = {{a0.x, a0.y, a0.z, a0.w}, {a1.x, a1.y, a1.z, a1.w}};
                const uint32_t bv[2][4] = {{b0.x, b0.y, b0.z, b0.w}, {b1.x, b1.y, b1.z, b1.w}};
#pragma unroll
                for (int p = 0; p < 2; p++)
#pragma unroll
                    for (int i = 0; i < 4; i++)
#pragma unroll
                        for (int qg = 0; qg < 2; qg++)
#pragma unroll
                            for (int j = 0; j < 4; j++)
                                acc[p][qg][i][j] =
                                    dp4a_s32(av[p][i], bv[qg][j], acc[p][qg][i][j]);
            }

            // phase 1: d values (overwrite acc), per-row tile min -> smem running min
#pragma unroll
            for (int p = 0; p < 2; p++)
#pragma unroll
                for (int i = 0; i < 4; i++) {
                    const int r = p * 64 + ty * 4 + i;
                    const float zz = zzs[r];
                    const float sz = szrs[r];
                    float mn = __int_as_float(0x7f800000);
#pragma unroll
                    for (int qg = 0; qg < 2; qg++)
#pragma unroll
                        for (int j = 0; j < 4; j++) {
                            const int c = qg * 64 + tx * 4 + j;
                            const float s = __int2float_rn(acc[p][qg][i][j]) * sz * secs[c];
                            const float d = (zz + ees[c]) - 2.0f * s;
                            acc[p][qg][i][j] = __float_as_int(d);
                            mn = fminf(mn, d);
                        }
#pragma unroll
                    for (int o = 1; o < 16; o <<= 1)
                        mn = fminf(mn, __shfl_xor_sync(0xffffffffu, mn, o));
                    if (tx == 0) atomicMin(&bdU[r], __float_as_uint(mn));
                }
            __syncthreads();

            // phase 2: collect candidates with d <= runmin + delta
            const int cb_ = code0 + t * 128;
#pragma unroll
            for (int p = 0; p < 2; p++)
#pragma unroll
                for (int i = 0; i < 4; i++) {
                    const int r = p * 64 + ty * 4 + i;
                    const float thr = __uint_as_float(bdU[r]) + DELTA;
                    const int grow = row0 + r;
#pragma unroll
                    for (int qg = 0; qg < 2; qg++)
#pragma unroll
                        for (int j = 0; j < 4; j++) {
                            const float d = __int_as_float(acc[p][qg][i][j]);
                            if (d <= thr) {
                                int sl = atomicAdd(&g_ncand[grow], 1);
                                if (sl < CAP) g_cand[grow * CAP + sl] = cb_ + qg * 64 + tx * 4 + j;
                            }
                        }
                }
            __syncthreads();
        }
    }
}

// -------- exact rescore of candidates (identical math to the rel_err=0 path) --------
__global__ void __launch_bounds__(256) vq_rescore_kernel(const float* __restrict__ z,
                                                         const float* __restrict__ cb) {
    __shared__ float zs[8][DD];
    const int tid = threadIdx.x;
    const int wid = tid >> 5, lid = tid & 31;
    const int row = blockIdx.x * 8 + wid;

    const float4* zr = reinterpret_cast<const float4*>(z + (size_t)row * DD);
    float4* zd = reinterpret_cast<float4*>(zs[wid]);
#pragma unroll
    for (int i = 0; i < 2; i++) zd[lid + 32 * i] = zr[lid + 32 * i];
    __syncwarp();

    const float zz = g_zz[row];
    const int nc = g_ncand[row];
    const bool full = (nc > CAP);           // overflow -> exact full scan
    const int n = full ? KCODES : nc;

    float bd = __int_as_float(0x7f800000);
    int bk = 0x7fffffff;
    for (int i = lid; i < n; i += 32) {
        const int code = full ? i : g_cand[row * CAP + i];
        const float4* e = reinterpret_cast<const float4*>(cb + (size_t)code * DD);
        float s = 0.f;
#pragma unroll
        for (int k4 = 0; k4 < DD / 4; k4++) {
            float4 ev = e[k4];
            float4 zv = zd[k4];
            s = fmaf(zv.x, ev.x, s); s = fmaf(zv.y, ev.y, s);
            s = fmaf(zv.z, ev.z, s); s = fmaf(zv.w, ev.w, s);
        }
        const float d = (zz + g_ee[code]) - 2.0f * s;
        if (d < bd || (d == bd && code < bk)) { bd = d; bk = code; }
    }
#pragma unroll
    for (int o = 16; o; o >>= 1) {
        float od = __shfl_xor_sync(0xffffffffu, bd, o);
        int ok = __shfl_xor_sync(0xffffffffu, bk, o);
        if (od < bd || (od == bd && ok < bk)) { bd = od; bk = ok; }
    }
    if (lid == 0) g_bestk[row] = bk;
}

// -------- output gather + straight-through + loss partials --------
__global__ void vq_output_kernel(const float* __restrict__ z, const float* __restrict__ cb,
                                 float* __restrict__ out) {
    const int tid = threadIdx.x;
    const size_t g4 = (size_t)blockIdx.x * 256 + tid;
    const int row = (int)(g4 >> 6);
    const int c4 = (int)(g4 & 63);
    const int idx = g_bestk[row];

    const float4 zv = reinterpret_cast<const float4*>(z)[g4];
    const float4 qv = reinterpret_cast<const float4*>(cb)[(size_t)idx * 64 + c4];

    float4 o;
    o.x = zv.x + (qv.x - zv.x);
    o.y = zv.y + (qv.y - zv.y);
    o.z = zv.z + (qv.z - zv.z);
    o.w = zv.w + (qv.w - zv.w);
    reinterpret_cast<float4*>(out)[g4] = o;

    const float dx = zv.x - qv.x, dy = zv.y - qv.y, dz = zv.z - qv.z, dw = zv.w - qv.w;
    float part = dx * dx;
    part = fmaf(dy, dy, part);
    part = fmaf(dz, dz, part);
    part = fmaf(dw, dw, part);

    __shared__ float sp[256];
    sp[tid] = part;
    __syncthreads();
#pragma unroll
    for (int s = 128; s; s >>= 1) {
        if (tid < s) sp[tid] += sp[tid + s];
        __syncthreads();
    }
    if (tid == 0) g_partial[blockIdx.x] = sp[0];
}

// -------- deterministic final loss reduction --------
__global__ void vq_loss_kernel(float* __restrict__ out, int out_size) {
    __shared__ double sm[256];
    const int tid = threadIdx.x;
    double s = 0.0;
    for (int i = tid; i < 8192; i += 256) s += (double)g_partial[i];
    sm[tid] = s;
    __syncthreads();
#pragma unroll
    for (int st = 128; st; st >>= 1) {
        if (tid < st) sm[tid] += sm[tid + st];
        __syncthreads();
    }
    if (tid == 0) {
        const float m = (float)(sm[0] / (double)QSIZE);
        const float vq = 0.25f * m + m;
        for (int i = QSIZE; i < out_size; i++) out[i] = vq;
    }
}

extern "C" void kernel_launch(void* const* d_in, const int* in_sizes, int n_in,
                              void* d_out, int out_size) {
    const float* z  = (const float*)d_in[0];
    const float* cb = (const float*)d_in[1];
    if (n_in >= 2 && in_sizes[0] == KCODES * DD && in_sizes[1] == NROWS * DD) {
        const float* t = z; z = cb; cb = t;
    }
    float* out = (float*)d_out;

    cudaFuncSetAttribute(vq_screen_kernel,
                         cudaFuncAttributeMaxDynamicSharedMemorySize, SM_TOTAL);

    float* zz_ptr;  cudaGetSymbolAddress((void**)&zz_ptr, g_zz);
    float* ee_ptr;  cudaGetSymbolAddress((void**)&ee_ptr, g_ee);
    float* szr_ptr; cudaGetSymbolAddress((void**)&szr_ptr, g_szr);
    float* sec_ptr; cudaGetSymbolAddress((void**)&sec_ptr, g_sec);
    uint32_t* zq_ptr; cudaGetSymbolAddress((void**)&zq_ptr, g_zqT);
    uint32_t* eq_ptr; cudaGetSymbolAddress((void**)&eq_ptr, g_eqT);

    vq_init_kernel<<<NROWS / 256, 256>>>();
    vq_norms_kernel<<<(NROWS * 32) / 256, 256>>>(z, zz_ptr, NROWS);
    vq_norms_kernel<<<(KCODES * 32) / 256, 256>>>(cb, ee_ptr, KCODES);
    vq_quant_kernel<<<(NROWS * 32) / 256, 256>>>(z, zq_ptr, szr_ptr, NROWS);
    vq_quant_kernel<<<(KCODES * 32) / 256, 256>>>(cb, eq_ptr, sec_ptr, KCODES);
    vq_screen_kernel<<<148, 256, SM_TOTAL>>>();
    vq_rescore_kernel<<<NROWS / 8, 256>>>(z, cb);
    vq_output_kernel<<<QSIZE / 1024, 256>>>(z, cb, out);
    vq_loss_kernel<<<1, 256>>>(out, out_size);
}

// round 7
// speedup vs baseline: 2.7633x; 2.7633x over previous
#include <cuda_runtime.h>
#include <cuda_fp16.h>
#include <cstdint>

#define NROWS 32768
#define KCODES 8192
#define DD 256
#define QSIZE (NROWS * DD)

#define TM 128
#define NSEG 2048
#define NUNITS ((NROWS / TM) * (KCODES / NSEG))   // 1024
#define NTPU (NSEG / 128)                         // 16 code-tiles per unit
#define CAP 64
#define DELTA 1e-3f

// smem byte offsets
#define SM_A   0                  // 64 KB  [kp128][row128] h2
#define SM_B0  65536              // 32 KB  [kk64][code128] h2
#define SM_B1  98304              // 32 KB
#define SM_ZZ  131072             // 512 B
#define SM_EE  131584             // 512 B
#define SM_BD  132096             // 512 B
#define SM_TOTAL 132608

// ---- device scratch ----
__device__ int      g_bestk[NROWS];
__device__ float    g_zz[NROWS];
__device__ float    g_ee[KCODES];
__device__ float    g_partial[8192];
__device__ int      g_work;
__device__ int      g_ncand[NROWS];
__device__ int      g_cand[NROWS * CAP];
__device__ uint32_t g_zh[NROWS * 128];    // [row>>7][kp][row&127]  (half2 k-pairs)
__device__ uint32_t g_eh[KCODES * 128];   // [code>>7][kp][code&127] (half2, e*8192)

__device__ __forceinline__ uint32_t smem_u32(const void* p) {
    uint32_t a;
    asm("{ .reg .u64 t; cvta.to.shared.u64 t, %1; cvt.u32.u64 %0, t; }" : "=r"(a) : "l"(p));
    return a;
}
__device__ __forceinline__ uint32_t h2u(__half2 h) { return *reinterpret_cast<uint32_t*>(&h); }
__device__ __forceinline__ __half2 u2h(uint32_t u) { return *reinterpret_cast<__half2*>(&u); }
#define CPASYNC16(dst, src) \
    asm volatile("cp.async.cg.shared.global [%0], [%1], 16;" :: "r"(dst), "l"(src))
#define CPCOMMIT() asm volatile("cp.async.commit_group;" ::: "memory")
#define CPWAIT1()  asm volatile("cp.async.wait_group 1;" ::: "memory")
#define CPWAIT0()  asm volatile("cp.async.wait_group 0;" ::: "memory")

// -------- init (graph-replayable) --------
__global__ void vq_init_kernel() {
    int i = blockIdx.x * 256 + threadIdx.x;
    g_ncand[i] = 0;
    if (i == 0) g_work = 0;
}

// -------- exact row squared-norms (matched reference; unchanged) --------
__global__ void vq_norms_kernel(const float* __restrict__ src, float* __restrict__ dst,
                                int nrows) {
    int w = (blockIdx.x * blockDim.x + threadIdx.x) >> 5;
    int lane = threadIdx.x & 31;
    if (w >= nrows) return;
    const float* row = src + (size_t)w * DD;
    float s = 0.f;
#pragma unroll
    for (int j = 0; j < DD / 32; j++) {
        float v = row[lane + 32 * j];
        s = fmaf(v, v, s);
    }
#pragma unroll
    for (int o = 16; o; o >>= 1) s += __shfl_xor_sync(0xffffffffu, s, o);
    if (lane == 0) dst[w] = s;
}

// -------- fp32 -> fp16x2 (k-pairs), transposed blocked layout --------
__global__ void vq_cvth_kernel(const float* __restrict__ src, uint32_t* __restrict__ dstT,
                               float scale, int n) {
    int w = (blockIdx.x * blockDim.x + threadIdx.x) >> 5;
    int lane = threadIdx.x & 31;
    if (w >= n) return;
    const float2* r2 = reinterpret_cast<const float2*>(src + (size_t)w * DD);
    const size_t base = (size_t)(w >> 7) * 16384 + (w & 127);
#pragma unroll
    for (int j = 0; j < 4; j++) {
        const int kp = lane + 32 * j;
        float2 v = r2[kp];
        __half2 h = __floats2half2_rn(v.x * scale, v.y * scale);
        dstT[base + (size_t)kp * 128] = h2u(h);
    }
}

// -------- HFMA2 fp16 screening: approx d, running-min candidate collection --------
// 256 thr = 16 tx (codes) x 16 ty (rows). Thread tile 8 rows x 8 codes.
// A tile full-K resident; B streamed in two 64-kp chunks per 128-code tile.
__global__ void __launch_bounds__(256, 1) vq_screen_kernel() {
    extern __shared__ char smem[];
    __shared__ int s_u;
    const uint32_t sbase = smem_u32(smem);
    const uint4* Aw4 = reinterpret_cast<const uint4*>(smem + SM_A);
    float* zzs = reinterpret_cast<float*>(smem + SM_ZZ);
    float* ees = reinterpret_cast<float*>(smem + SM_EE);
    unsigned int* bdU = reinterpret_cast<unsigned int*>(smem + SM_BD);

    const int tid = threadIdx.x;
    const int tx = tid & 15;
    const int ty = tid >> 4;
    const float sfold = -2.0f / 8192.0f;     // folds e-scale + the -2 factor

    for (;;) {
        if (tid == 0) s_u = atomicAdd(&g_work, 1);
        __syncthreads();
        const int u = s_u;
        if (u >= NUNITS) return;
        const int rb = u & 255;
        const int cq = u >> 8;
        const int row0 = rb * TM;
        const int code0 = cq * NSEG;

        // group G0: A tile (64KB) + B chunk 0 (32KB)
        {
            const uint32_t* asrc = g_zh + (size_t)rb * 16384;
#pragma unroll
            for (int i = 0; i < 16; i++) {
                int f = tid + 256 * i;
                CPASYNC16(sbase + SM_A + f * 16, asrc + f * 4);
            }
            const uint32_t* bsrc = g_eh + (size_t)(cq * 16) * 16384;
#pragma unroll
            for (int i = 0; i < 8; i++) {
                int f = tid + 256 * i;
                CPASYNC16(sbase + SM_B0 + f * 16, bsrc + f * 4);
            }
            CPCOMMIT();
        }
        if (tid < 128) {
            zzs[tid] = g_zz[row0 + tid];
            bdU[tid] = 0x7f800000u;
        }

        for (int t = 0; t < NTPU; t++) {
            if (tid < 128) ees[tid] = g_ee[code0 + t * 128 + tid];

            uint32_t acc[8][8];
            float facc[8][8];
#pragma unroll
            for (int i = 0; i < 8; i++)
#pragma unroll
                for (int j = 0; j < 8; j++) { acc[i][j] = 0u; facc[i][j] = 0.f; }

#pragma unroll 1
            for (int c = 0; c < 2; c++) {
                const int ci = t * 2 + c;
                // prefetch chunk ci+1 into the other buffer
                if (ci + 1 < 2 * NTPU) {
                    const uint32_t bb = sbase + (((ci + 1) & 1) ? SM_B1 : SM_B0);
                    const uint32_t* src = g_eh +
                        (size_t)(cq * 16 + ((ci + 1) >> 1)) * 16384 + ((ci + 1) & 1) * 8192;
#pragma unroll
                    for (int i = 0; i < 8; i++) {
                        int f = tid + 256 * i;
                        CPASYNC16(bb + f * 16, src + f * 4);
                    }
                    CPCOMMIT();
                    CPWAIT1();          // current chunk resident
                } else {
                    CPWAIT0();
                }
                __syncthreads();        // visible to all; also A/zz on first pass

                const uint4* Bw4 = reinterpret_cast<const uint4*>(
                    smem + ((ci & 1) ? SM_B1 : SM_B0));
                const int kpA0 = c * 64;

#pragma unroll 8
                for (int kk = 0; kk < 64; kk++) {
                    uint4 a0 = Aw4[(kpA0 + kk) * 32 + ty * 2];
                    uint4 a1 = Aw4[(kpA0 + kk) * 32 + ty * 2 + 1];
                    uint4 b0 = Bw4[kk * 32 + tx * 2];
                    uint4 b1 = Bw4[kk * 32 + tx * 2 + 1];
                    const __half2 ar[8] = {u2h(a0.x), u2h(a0.y), u2h(a0.z), u2h(a0.w),
                                           u2h(a1.x), u2h(a1.y), u2h(a1.z), u2h(a1.w)};
                    const __half2 br[8] = {u2h(b0.x), u2h(b0.y), u2h(b0.z), u2h(b0.w),
                                           u2h(b1.x), u2h(b1.y), u2h(b1.z), u2h(b1.w)};
#pragma unroll
                    for (int i = 0; i < 8; i++)
#pragma unroll
                        for (int j = 0; j < 8; j++)
                            acc[i][j] = h2u(__hfma2(ar[i], br[j], u2h(acc[i][j])));
                }

                // drain fp16 accumulators into fp32 (bounds the rounding chain)
#pragma unroll
                for (int i = 0; i < 8; i++)
#pragma unroll
                    for (int j = 0; j < 8; j++) {
                        float2 f = __half22float2(u2h(acc[i][j]));
                        facc[i][j] += f.x + f.y;
                        acc[i][j] = 0u;
                    }
                __syncthreads();        // compute done before next prefetch overwrites
            }

            // phase 1: d values (store into acc bits), per-row tile min -> running min
#pragma unroll
            for (int i = 0; i < 8; i++) {
                const int r = ty * 8 + i;
                const float zz = zzs[r];
                float mn = __int_as_float(0x7f800000);
#pragma unroll
                for (int j = 0; j < 8; j++) {
                    const int cloc = tx * 8 + j;
                    const float d = fmaf(facc[i][j], sfold, zz + ees[cloc]);
                    acc[i][j] = __float_as_uint(d);
                    mn = fminf(mn, d);
                }
#pragma unroll
                for (int o = 1; o < 16; o <<= 1)
                    mn = fminf(mn, __shfl_xor_sync(0xffffffffu, mn, o));
                if (tx == 0) atomicMin(&bdU[r], __float_as_uint(mn));
            }
            __syncthreads();

            // phase 2: collect candidates with d <= runmin + delta
            const int cb_ = code0 + t * 128;
#pragma unroll
            for (int i = 0; i < 8; i++) {
                const int r = ty * 8 + i;
                const float thr = __uint_as_float(bdU[r]) + DELTA;
                const int grow = row0 + r;
#pragma unroll
                for (int j = 0; j < 8; j++) {
                    const float d = __uint_as_float(acc[i][j]);
                    if (d <= thr) {
                        int sl = atomicAdd(&g_ncand[grow], 1);
                        if (sl < CAP) g_cand[grow * CAP + sl] = cb_ + tx * 8 + j;
                    }
                }
            }
            __syncthreads();            // phase2 done before next tile's ees/B writes
        }
    }
}

// -------- exact rescore of candidates (identical math to the rel_err=0 path) --------
__global__ void __launch_bounds__(256) vq_rescore_kernel(const float* __restrict__ z,
                                                         const float* __restrict__ cb) {
    __shared__ float zs[8][DD];
    const int tid = threadIdx.x;
    const int wid = tid >> 5, lid = tid & 31;
    const int row = blockIdx.x * 8 + wid;

    const float4* zr = reinterpret_cast<const float4*>(z + (size_t)row * DD);
    float4* zd = reinterpret_cast<float4*>(zs[wid]);
#pragma unroll
    for (int i = 0; i < 2; i++) zd[lid + 32 * i] = zr[lid + 32 * i];
    __syncwarp();

    const float zz = g_zz[row];
    const int nc = g_ncand[row];
    const bool full = (nc > CAP);           // overflow -> exact full scan
    const int n = full ? KCODES : nc;

    float bd = __int_as_float(0x7f800000);
    int bk = 0x7fffffff;
    for (int i = lid; i < n; i += 32) {
        const int code = full ? i : g_cand[row * CAP + i];
        const float4* e = reinterpret_cast<const float4*>(cb + (size_t)code * DD);
        float s = 0.f;
#pragma unroll
        for (int k4 = 0; k4 < DD / 4; k4++) {
            float4 ev = e[k4];
            float4 zv = zd[k4];
            s = fmaf(zv.x, ev.x, s); s = fmaf(zv.y, ev.y, s);
            s = fmaf(zv.z, ev.z, s); s = fmaf(zv.w, ev.w, s);
        }
        const float d = (zz + g_ee[code]) - 2.0f * s;
        if (d < bd || (d == bd && code < bk)) { bd = d; bk = code; }
    }
#pragma unroll
    for (int o = 16; o; o >>= 1) {
        float od = __shfl_xor_sync(0xffffffffu, bd, o);
        int ok = __shfl_xor_sync(0xffffffffu, bk, o);
        if (od < bd || (od == bd && ok < bk)) { bd = od; bk = ok; }
    }
    if (lid == 0) g_bestk[row] = bk;
}

// -------- output gather + straight-through + loss partials --------
__global__ void vq_output_kernel(const float* __restrict__ z, const float* __restrict__ cb,
                                 float* __restrict__ out) {
    const int tid = threadIdx.x;
    const size_t g4 = (size_t)blockIdx.x * 256 + tid;
    const int row = (int)(g4 >> 6);
    const int c4 = (int)(g4 & 63);
    const int idx = g_bestk[row];

    const float4 zv = reinterpret_cast<const float4*>(z)[g4];
    const float4 qv = reinterpret_cast<const float4*>(cb)[(size_t)idx * 64 + c4];

    float4 o;
    o.x = zv.x + (qv.x - zv.x);
    o.y = zv.y + (qv.y - zv.y);
    o.z = zv.z + (qv.z - zv.z);
    o.w = zv.w + (qv.w - zv.w);
    reinterpret_cast<float4*>(out)[g4] = o;

    const float dx = zv.x - qv.x, dy = zv.y - qv.y, dz = zv.z - qv.z, dw = zv.w - qv.w;
    float part = dx * dx;
    part = fmaf(dy, dy, part);
    part = fmaf(dz, dz, part);
    part = fmaf(dw, dw, part);

    __shared__ float sp[256];
    sp[tid] = part;
    __syncthreads();
#pragma unroll
    for (int s = 128; s; s >>= 1) {
        if (tid < s) sp[tid] += sp[tid + s];
        __syncthreads();
    }
    if (tid == 0) g_partial[blockIdx.x] = sp[0];
}

// -------- deterministic final loss reduction --------
__global__ void vq_loss_kernel(float* __restrict__ out, int out_size) {
    __shared__ double sm[256];
    const int tid = threadIdx.x;
    double s = 0.0;
    for (int i = tid; i < 8192; i += 256) s += (double)g_partial[i];
    sm[tid] = s;
    __syncthreads();
#pragma unroll
    for (int st = 128; st; st >>= 1) {
        if (tid < st) sm[tid] += sm[tid + st];
        __syncthreads();
    }
    if (tid == 0) {
        const float m = (float)(sm[0] / (double)QSIZE);
        const float vq = 0.25f * m + m;
        for (int i = QSIZE; i < out_size; i++) out[i] = vq;
    }
}

extern "C" void kernel_launch(void* const* d_in, const int* in_sizes, int n_in,
                              void* d_out, int out_size) {
    const float* z  = (const float*)d_in[0];
    const float* cb = (const float*)d_in[1];
    if (n_in >= 2 && in_sizes[0] == KCODES * DD && in_sizes[1] == NROWS * DD) {
        const float* t = z; z = cb; cb = t;
    }
    float* out = (float*)d_out;

    cudaFuncSetAttribute(vq_screen_kernel,
                         cudaFuncAttributeMaxDynamicSharedMemorySize, SM_TOTAL);

    float* zz_ptr; cudaGetSymbolAddress((void**)&zz_ptr, g_zz);
    float* ee_ptr; cudaGetSymbolAddress((void**)&ee_ptr, g_ee);
    uint32_t* zh_ptr; cudaGetSymbolAddress((void**)&zh_ptr, g_zh);
    uint32_t* eh_ptr; cudaGetSymbolAddress((void**)&eh_ptr, g_eh);

    vq_init_kernel<<<NROWS / 256, 256>>>();
    vq_norms_kernel<<<(NROWS * 32) / 256, 256>>>(z, zz_ptr, NROWS);
    vq_norms_kernel<<<(KCODES * 32) / 256, 256>>>(cb, ee_ptr, KCODES);
    vq_cvth_kernel<<<(NROWS * 32) / 256, 256>>>(z, zh_ptr, 1.0f, NROWS);
    vq_cvth_kernel<<<(KCODES * 32) / 256, 256>>>(cb, eh_ptr, 8192.0f, KCODES);
    vq_screen_kernel<<<148, 256, SM_TOTAL>>>();
    vq_rescore_kernel<<<NROWS / 8, 256>>>(z, cb);
    vq_output_kernel<<<QSIZE / 1024, 256>>>(z, cb, out);
    vq_loss_kernel<<<1, 256>>>(out, out_size);
}

// round 8
// speedup vs baseline: 2.7845x; 1.0077x over previous
#include <cuda_runtime.h>
#include <cuda_fp16.h>
#include <cstdint>

#define NROWS 32768
#define KCODES 8192
#define DD 256
#define QSIZE (NROWS * DD)

#define TM 128
#define NSEG 2048
#define NUNITS ((NROWS / TM) * (KCODES / NSEG))   // 1024
#define NTPU (NSEG / 128)                         // 16 code-tiles per unit
#define CAP 64
#define DELTA 1e-3f

// smem byte offsets
#define SM_A   0                  // 64 KB  [kp128][row128] h2
#define SM_B0  65536              // 32 KB  [kk64][code128] h2
#define SM_B1  98304              // 32 KB
#define SM_ZZ  131072             // 512 B
#define SM_EE  131584             // 512 B
#define SM_BD  132096             // 512 B
#define SM_TOTAL 132608

// ---- device scratch ----
__device__ int      g_bestk[NROWS];
__device__ float    g_zz[NROWS];
__device__ float    g_ee[KCODES];
__device__ float    g_partial[8192];
__device__ int      g_work;
__device__ int      g_ncand[NROWS];
__device__ int      g_cand[NROWS * CAP];
__device__ uint32_t g_zh[NROWS * 128];    // [row>>7][kp][row&127]  (half2 k-pairs)
__device__ uint32_t g_eh[KCODES * 128];   // [code>>7][kp][code&127] (half2, e*8192)

__device__ __forceinline__ uint32_t smem_u32(const void* p) {
    uint32_t a;
    asm("{ .reg .u64 t; cvta.to.shared.u64 t, %1; cvt.u32.u64 %0, t; }" : "=r"(a) : "l"(p));
    return a;
}
__device__ __forceinline__ uint32_t h2u(__half2 h) { return *reinterpret_cast<uint32_t*>(&h); }
__device__ __forceinline__ __half2 u2h(uint32_t u) { return *reinterpret_cast<__half2*>(&u); }
#define CPASYNC16(dst, src) \
    asm volatile("cp.async.cg.shared.global [%0], [%1], 16;" :: "r"(dst), "l"(src))
#define CPCOMMIT() asm volatile("cp.async.commit_group;" ::: "memory")
#define CPWAIT1()  asm volatile("cp.async.wait_group 1;" ::: "memory")
#define CPWAIT0()  asm volatile("cp.async.wait_group 0;" ::: "memory")

// -------- init (graph-replayable) --------
__global__ void vq_init_kernel() {
    int i = blockIdx.x * 256 + threadIdx.x;
    g_ncand[i] = 0;
    if (i == 0) g_work = 0;
}

// -------- exact row squared-norms (matched reference; unchanged) --------
__global__ void vq_norms_kernel(const float* __restrict__ src, float* __restrict__ dst,
                                int nrows) {
    int w = (blockIdx.x * blockDim.x + threadIdx.x) >> 5;
    int lane = threadIdx.x & 31;
    if (w >= nrows) return;
    const float* row = src + (size_t)w * DD;
    float s = 0.f;
#pragma unroll
    for (int j = 0; j < DD / 32; j++) {
        float v = row[lane + 32 * j];
        s = fmaf(v, v, s);
    }
#pragma unroll
    for (int o = 16; o; o >>= 1) s += __shfl_xor_sync(0xffffffffu, s, o);
    if (lane == 0) dst[w] = s;
}

// -------- fp32 -> fp16x2 (k-pairs), transposed blocked layout --------
__global__ void vq_cvth_kernel(const float* __restrict__ src, uint32_t* __restrict__ dstT,
                               float scale, int n) {
    int w = (blockIdx.x * blockDim.x + threadIdx.x) >> 5;
    int lane = threadIdx.x & 31;
    if (w >= n) return;
    const float2* r2 = reinterpret_cast<const float2*>(src + (size_t)w * DD);
    const size_t base = (size_t)(w >> 7) * 16384 + (w & 127);
#pragma unroll
    for (int j = 0; j < 4; j++) {
        const int kp = lane + 32 * j;
        float2 v = r2[kp];
        __half2 h = __floats2half2_rn(v.x * scale, v.y * scale);
        dstT[base + (size_t)kp * 128] = h2u(h);
    }
}

// -------- HFMA2 fp16 screening: approx d, running-min candidate collection --------
// 256 thr = 16 tx (codes) x 16 ty (rows). Thread tile 8 rows x 8 codes.
// Single fp16 accumulator chain per (row,code) across the tile's full K=256
// (128 sequential hfma2) -> no fp32 drain array -> no register spills.
__global__ void __launch_bounds__(256, 1) vq_screen_kernel() {
    extern __shared__ char smem[];
    __shared__ int s_u;
    const uint32_t sbase = smem_u32(smem);
    const uint4* Aw4 = reinterpret_cast<const uint4*>(smem + SM_A);
    float* zzs = reinterpret_cast<float*>(smem + SM_ZZ);
    float* ees = reinterpret_cast<float*>(smem + SM_EE);
    unsigned int* bdU = reinterpret_cast<unsigned int*>(smem + SM_BD);

    const int tid = threadIdx.x;
    const int tx = tid & 15;
    const int ty = tid >> 4;
    const float sfold = -2.0f / 8192.0f;     // folds e-scale + the -2 factor

    for (;;) {
        if (tid == 0) s_u = atomicAdd(&g_work, 1);
        __syncthreads();
        const int u = s_u;
        if (u >= NUNITS) return;
        const int rb = u & 255;
        const int cq = u >> 8;
        const int row0 = rb * TM;
        const int code0 = cq * NSEG;

        // group G0: A tile (64KB) + B chunk 0 (32KB)
        {
            const uint32_t* asrc = g_zh + (size_t)rb * 16384;
#pragma unroll
            for (int i = 0; i < 16; i++) {
                int f = tid + 256 * i;
                CPASYNC16(sbase + SM_A + f * 16, asrc + f * 4);
            }
            const uint32_t* bsrc = g_eh + (size_t)(cq * 16) * 16384;
#pragma unroll
            for (int i = 0; i < 8; i++) {
                int f = tid + 256 * i;
                CPASYNC16(sbase + SM_B0 + f * 16, bsrc + f * 4);
            }
            CPCOMMIT();
        }
        if (tid < 128) {
            zzs[tid] = g_zz[row0 + tid];
            bdU[tid] = 0x7f800000u;
        }

        for (int t = 0; t < NTPU; t++) {
            if (tid < 128) ees[tid] = g_ee[code0 + t * 128 + tid];

            uint32_t acc[8][8];
#pragma unroll
            for (int i = 0; i < 8; i++)
#pragma unroll
                for (int j = 0; j < 8; j++) acc[i][j] = 0u;

#pragma unroll 1
            for (int c = 0; c < 2; c++) {
                const int ci = t * 2 + c;
                // prefetch chunk ci+1 into the other buffer
                if (ci + 1 < 2 * NTPU) {
                    const uint32_t bb = sbase + (((ci + 1) & 1) ? SM_B1 : SM_B0);
                    const uint32_t* src = g_eh +
                        (size_t)(cq * 16 + ((ci + 1) >> 1)) * 16384 + ((ci + 1) & 1) * 8192;
#pragma unroll
                    for (int i = 0; i < 8; i++) {
                        int f = tid + 256 * i;
                        CPASYNC16(bb + f * 16, src + f * 4);
                    }
                    CPCOMMIT();
                    CPWAIT1();          // current chunk resident
                } else {
                    CPWAIT0();
                }
                __syncthreads();        // visible to all; also A/zz on first pass

                const uint4* Bw4 = reinterpret_cast<const uint4*>(
                    smem + ((ci & 1) ? SM_B1 : SM_B0));
                const int kpA0 = c * 64;

#pragma unroll 8
                for (int kk = 0; kk < 64; kk++) {
                    uint4 a0 = Aw4[(kpA0 + kk) * 32 + ty * 2];
                    uint4 a1 = Aw4[(kpA0 + kk) * 32 + ty * 2 + 1];
                    uint4 b0 = Bw4[kk * 32 + tx * 2];
                    uint4 b1 = Bw4[kk * 32 + tx * 2 + 1];
                    const __half2 ar[8] = {u2h(a0.x), u2h(a0.y), u2h(a0.z), u2h(a0.w),
                                           u2h(a1.x), u2h(a1.y), u2h(a1.z), u2h(a1.w)};
                    const __half2 br[8] = {u2h(b0.x), u2h(b0.y), u2h(b0.z), u2h(b0.w),
                                           u2h(b1.x), u2h(b1.y), u2h(b1.z), u2h(b1.w)};
#pragma unroll
                    for (int i = 0; i < 8; i++)
#pragma unroll
                        for (int j = 0; j < 8; j++)
                            acc[i][j] = h2u(__hfma2(ar[i], br[j], u2h(acc[i][j])));
                }
                __syncthreads();        // compute done before next prefetch overwrites
            }

            // phase 1: convert acc -> d (store bits back into acc), running min
#pragma unroll
            for (int i = 0; i < 8; i++) {
                const int r = ty * 8 + i;
                const float zz = zzs[r];
                float mn = __int_as_float(0x7f800000);
#pragma unroll
                for (int j = 0; j < 8; j++) {
                    const int cloc = tx * 8 + j;
                    float2 f = __half22float2(u2h(acc[i][j]));
                    const float d = fmaf(f.x + f.y, sfold, zz + ees[cloc]);
                    acc[i][j] = __float_as_uint(d);
                    mn = fminf(mn, d);
                }
#pragma unroll
                for (int o = 1; o < 16; o <<= 1)
                    mn = fminf(mn, __shfl_xor_sync(0xffffffffu, mn, o));
                if (tx == 0) atomicMin(&bdU[r], __float_as_uint(mn));
            }
            __syncthreads();

            // phase 2: collect candidates with d <= runmin + delta
            const int cb_ = code0 + t * 128;
#pragma unroll
            for (int i = 0; i < 8; i++) {
                const int r = ty * 8 + i;
                const float thr = __uint_as_float(bdU[r]) + DELTA;
                const int grow = row0 + r;
#pragma unroll
                for (int j = 0; j < 8; j++) {
                    const float d = __uint_as_float(acc[i][j]);
                    if (d <= thr) {
                        int sl = atomicAdd(&g_ncand[grow], 1);
                        if (sl < CAP) g_cand[grow * CAP + sl] = cb_ + tx * 8 + j;
                    }
                }
            }
            __syncthreads();            // phase2 done before next tile's ees/B writes
        }
    }
}

// -------- exact rescore of candidates (identical math to the rel_err=0 path) --------
__global__ void __launch_bounds__(256) vq_rescore_kernel(const float* __restrict__ z,
                                                         const float* __restrict__ cb) {
    __shared__ float zs[8][DD];
    const int tid = threadIdx.x;
    const int wid = tid >> 5, lid = tid & 31;
    const int row = blockIdx.x * 8 + wid;

    const float4* zr = reinterpret_cast<const float4*>(z + (size_t)row * DD);
    float4* zd = reinterpret_cast<float4*>(zs[wid]);
#pragma unroll
    for (int i = 0; i < 2; i++) zd[lid + 32 * i] = zr[lid + 32 * i];
    __syncwarp();

    const float zz = g_zz[row];
    const int nc = g_ncand[row];
    const bool full = (nc > CAP);           // overflow -> exact full scan
    const int n = full ? KCODES : nc;

    float bd = __int_as_float(0x7f800000);
    int bk = 0x7fffffff;
    for (int i = lid; i < n; i += 32) {
        const int code = full ? i : g_cand[row * CAP + i];
        const float4* e = reinterpret_cast<const float4*>(cb + (size_t)code * DD);
        float s = 0.f;
#pragma unroll
        for (int k4 = 0; k4 < DD / 4; k4++) {
            float4 ev = e[k4];
            float4 zv = zd[k4];
            s = fmaf(zv.x, ev.x, s); s = fmaf(zv.y, ev.y, s);
            s = fmaf(zv.z, ev.z, s); s = fmaf(zv.w, ev.w, s);
        }
        const float d = (zz + g_ee[code]) - 2.0f * s;
        if (d < bd || (d == bd && code < bk)) { bd = d; bk = code; }
    }
#pragma unroll
    for (int o = 16; o; o >>= 1) {
        float od = __shfl_xor_sync(0xffffffffu, bd, o);
        int ok = __shfl_xor_sync(0xffffffffu, bk, o);
        if (od < bd || (od == bd && ok < bk)) { bd = od; bk = ok; }
    }
    if (lid == 0) g_bestk[row] = bk;
}

// -------- output gather + straight-through + loss partials --------
__global__ void vq_output_kernel(const float* __restrict__ z, const float* __restrict__ cb,
                                 float* __restrict__ out) {
    const int tid = threadIdx.x;
    const size_t g4 = (size_t)blockIdx.x * 256 + tid;
    const int row = (int)(g4 >> 6);
    const int c4 = (int)(g4 & 63);
    const int idx = g_bestk[row];

    const float4 zv = reinterpret_cast<const float4*>(z)[g4];
    const float4 qv = reinterpret_cast<const float4*>(cb)[(size_t)idx * 64 + c4];

    float4 o;
    o.x = zv.x + (qv.x - zv.x);
    o.y = zv.y + (qv.y - zv.y);
    o.z = zv.z + (qv.z - zv.z);
    o.w = zv.w + (qv.w - zv.w);
    reinterpret_cast<float4*>(out)[g4] = o;

    const float dx = zv.x - qv.x, dy = zv.y - qv.y, dz = zv.z - qv.z, dw = zv.w - qv.w;
    float part = dx * dx;
    part = fmaf(dy, dy, part);
    part = fmaf(dz, dz, part);
    part = fmaf(dw, dw, part);

    __shared__ float sp[256];
    sp[tid] = part;
    __syncthreads();
#pragma unroll
    for (int s = 128; s; s >>= 1) {
        if (tid < s) sp[tid] += sp[tid + s];
        __syncthreads();
    }
    if (tid == 0) g_partial[blockIdx.x] = sp[0];
}

// -------- deterministic final loss reduction --------
__global__ void vq_loss_kernel(float* __restrict__ out, int out_size) {
    __shared__ double sm[256];
    const int tid = threadIdx.x;
    double s = 0.0;
    for (int i = tid; i < 8192; i += 256) s += (double)g_partial[i];
    sm[tid] = s;
    __syncthreads();
#pragma unroll
    for (int st = 128; st; st >>= 1) {
        if (tid < st) sm[tid] += sm[tid + st];
        __syncthreads();
    }
    if (tid == 0) {
        const float m = (float)(sm[0] / (double)QSIZE);
        const float vq = 0.25f * m + m;
        for (int i = QSIZE; i < out_size; i++) out[i] = vq;
    }
}

extern "C" void kernel_launch(void* const* d_in, const int* in_sizes, int n_in,
                              void* d_out, int out_size) {
    const float* z  = (const float*)d_in[0];
    const float* cb = (const float*)d_in[1];
    if (n_in >= 2 && in_sizes[0] == KCODES * DD && in_sizes[1] == NROWS * DD) {
        const float* t = z; z = cb; cb = t;
    }
    float* out = (float*)d_out;

    cudaFuncSetAttribute(vq_screen_kernel,
                         cudaFuncAttributeMaxDynamicSharedMemorySize, SM_TOTAL);

    float* zz_ptr; cudaGetSymbolAddress((void**)&zz_ptr, g_zz);
    float* ee_ptr; cudaGetSymbolAddress((void**)&ee_ptr, g_ee);
    uint32_t* zh_ptr; cudaGetSymbolAddress((void**)&zh_ptr, g_zh);
    uint32_t* eh_ptr; cudaGetSymbolAddress((void**)&eh_ptr, g_eh);

    vq_init_kernel<<<NROWS / 256, 256>>>();
    vq_norms_kernel<<<(NROWS * 32) / 256, 256>>>(z, zz_ptr, NROWS);
    vq_norms_kernel<<<(KCODES * 32) / 256, 256>>>(cb, ee_ptr, KCODES);
    vq_cvth_kernel<<<(NROWS * 32) / 256, 256>>>(z, zh_ptr, 1.0f, NROWS);
    vq_cvth_kernel<<<(KCODES * 32) / 256, 256>>>(cb, eh_ptr, 8192.0f, KCODES);
    vq_screen_kernel<<<148, 256, SM_TOTAL>>>();
    vq_rescore_kernel<<<NROWS / 8, 256>>>(z, cb);
    vq_output_kernel<<<QSIZE / 1024, 256>>>(z, cb, out);
    vq_loss_kernel<<<1, 256>>>(out, out_size);
}

// round 9
// speedup vs baseline: 23.5997x; 8.4752x over previous
#include <cuda_runtime.h>
#include <cstdint>

#define NROWS 32768
#define KCODES 8192
#define DD 256
#define QSIZE (NROWS * DD)

#define MT 128                  // rows per unit
#define NSEG 2048               // codes per unit
#define NUNITS ((NROWS / MT) * (KCODES / NSEG))   // 1024
#define NTPU (NSEG / 128)       // 16 n-tiles (128 codes) per unit
#define NCH (NTPU * 8)          // 128 B-chunks (32 k x 128 codes) per unit

// smem: A image 131072 B, then 4 B-chunk buffers of 16384 B
#define SMB_B0 131072
#define SM_TOTAL (131072 + 4 * 16384)   // 196608

// ---- device scratch ----
__device__ unsigned long long g_best[NROWS];
__device__ float g_zz[NROWS];
__device__ float g_ee[KCODES];
__device__ float g_partial[8192];
__device__ int   g_work;
__device__ float g_zT[NROWS * DD];      // per 128-row block: [k][swizzled m] image
__device__ float g_ebT[KCODES * DD];    // per (tile,kc) chunk: 4096-float smem image

#define DUPB(dst, s)  asm("mov.b64 %0, {%1, %1};" : "=l"(dst) : "f"(s))
#define FFMA2(acc, a, b) asm("fma.rn.f32x2 %0, %1, %2, %0;" : "+l"(acc) : "l"(a), "l"(b))
#define UNPK(lo, hi, v) asm("mov.b64 {%0, %1}, %2;" : "=f"(lo), "=f"(hi) : "l"(v))

__device__ __forceinline__ uint32_t smem_u32(const void* p) {
    uint32_t a;
    asm("{ .reg .u64 t; cvta.to.shared.u64 t, %1; cvt.u32.u64 %0, t; }" : "=r"(a) : "l"(p));
    return a;
}
#define CPASYNC16(dst, src) \
    asm volatile("cp.async.cg.shared.global [%0], [%1], 16;" :: "r"(dst), "l"(src))
#define CPCOMMIT() asm volatile("cp.async.commit_group;" ::: "memory")
#define CPWAIT2()  asm volatile("cp.async.wait_group 2;" ::: "memory")
#define CPWAIT1()  asm volatile("cp.async.wait_group 1;" ::: "memory")
#define CPWAIT0()  asm volatile("cp.async.wait_group 0;" ::: "memory")

// -------- init (graph-replayable) --------
__global__ void vq_init_kernel() {
    int i = blockIdx.x * 256 + threadIdx.x;
    g_best[i] = 0xFFFFFFFFFFFFFFFFULL;
    if (i == 0) g_work = 0;
}

// -------- exact row squared-norms (matched reference; unchanged) --------
__global__ void vq_norms_kernel(const float* __restrict__ src, float* __restrict__ dst,
                                int nrows) {
    int w = (blockIdx.x * blockDim.x + threadIdx.x) >> 5;
    int lane = threadIdx.x & 31;
    if (w >= nrows) return;
    const float* row = src + (size_t)w * DD;
    float s = 0.f;
#pragma unroll
    for (int j = 0; j < DD / 32; j++) {
        float v = row[lane + 32 * j];
        s = fmaf(v, v, s);
    }
#pragma unroll
    for (int o = 16; o; o >>= 1) s += __shfl_xor_sync(0xffffffffu, s, o);
    if (lane == 0) dst[w] = s;
}

// -------- prep: z -> transposed+swizzled block images (half-block per CTA) --------
__global__ void vq_prep_z(const float* __restrict__ z) {
    __shared__ alignas(16) float img[16384];   // 64 KB: 128 k x 128 m image half
    const int rb = blockIdx.x >> 1;
    const int h = blockIdx.x & 1;
    const int tid = threadIdx.x;
#pragma unroll
    for (int i = 0; i < 16; i++) {
        int f = tid + 256 * i;
        int m = f >> 5, k4l = f & 31;          // local k-group 0..31
        float4 v = *reinterpret_cast<const float4*>(
            z + ((size_t)(rb * 128 + m)) * DD + h * 128 + k4l * 4);
        int colg = (m >> 2) ^ (k4l & 7);       // (k4&7): h*32 is 0 mod 8
        float* p = img + (k4l * 4) * 128 + colg * 4 + (m & 3);
        p[0] = v.x; p[128] = v.y; p[256] = v.z; p[384] = v.w;
    }
    __syncthreads();
    float* dst = g_zT + (size_t)rb * 32768 + h * 16384;
#pragma unroll
    for (int i = 0; i < 16; i++) {
        int f = tid + 256 * i;
        *reinterpret_cast<float4*>(dst + f * 4) =
            *reinterpret_cast<const float4*>(img + f * 4);
    }
}

// -------- prep: codebook -> per-(tile,kc) 16KB chunk images --------
__global__ void vq_prep_cb(const float* __restrict__ cb) {
    __shared__ alignas(16) float img[4096];    // 16 KB
    const int tile = blockIdx.x >> 3;
    const int kc = blockIdx.x & 7;
    const int tid = threadIdx.x;
#pragma unroll
    for (int i = 0; i < 4; i++) {
        int f = tid + 256 * i;
        int n = f >> 3, bk4 = f & 7;
        float4 v = *reinterpret_cast<const float4*>(
            cb + ((size_t)(tile * 128 + n)) * DD + kc * 32 + bk4 * 4);
        int colg = (n >> 2) ^ bk4;
        float* p = img + (bk4 * 4) * 128 + colg * 4 + (n & 3);
        p[0] = v.x; p[128] = v.y; p[256] = v.z; p[384] = v.w;
    }
    __syncthreads();
    float* dst = g_ebT + ((size_t)tile * 8 + kc) * 4096;
#pragma unroll
    for (int i = 0; i < 4; i++) {
        int f = tid + 256 * i;
        *reinterpret_cast<float4*>(dst + f * 4) =
            *reinterpret_cast<const float4*>(img + f * 4);
    }
}

// -------- main exact FFMA2 distance-argmin (R2 engine + cp.async pipeline) --------
// 256 thr = 16 tx (codes) x 16 ty (rows). Thread tile 8 rows x 8 codes,
// 32 b64 accumulators (4 row-pairs x 8 codes). Sequential per-lane fp32 chains.
__global__ void __launch_bounds__(256, 1) vq_argmin_kernel() {
    extern __shared__ float smem[];
    float* At = smem;                          // 32768 floats (128 rows x 256 k image)
    __shared__ int s_u;
    const uint32_t sbase = smem_u32(smem);

    const int tid = threadIdx.x;
    const int tx = tid & 15;
    const int ty = tid >> 4;

    for (;;) {
        __syncthreads();                       // prior unit's smem reads done
        if (tid == 0) s_u = atomicAdd(&g_work, 1);
        __syncthreads();
        const int u = s_u;
        if (u >= NUNITS) return;
        const int rb = u & 255;
        const int cseg = u >> 8;
        const int row0 = rb * MT;
        const int cseg0 = cseg * NSEG;

        // issue A image (1 group) + first 3 B chunks (3 groups)
        {
            const float* asrc = g_zT + (size_t)rb * 32768;
#pragma unroll
            for (int i = 0; i < 32; i++) {
                int f = tid + 256 * i;         // 8192 x 16B = 128 KB
                CPASYNC16(sbase + f * 16, asrc + f * 4);
            }
            CPCOMMIT();
#pragma unroll
            for (int c = 0; c < 3; c++) {      // chunks ci=0,1,2 (nt=0, kc=c)
                const float* bsrc = g_ebT + ((size_t)(cseg * NTPU) * 8 + c) * 4096;
                uint32_t bb = sbase + SMB_B0 + c * 16384;
#pragma unroll
                for (int i = 0; i < 4; i++) {
                    int f = tid + 256 * i;
                    CPASYNC16(bb + f * 16, bsrc + f * 4);
                }
                CPCOMMIT();
            }
        }

        float zzr[8], bd[8];
        int bk[8];
#pragma unroll
        for (int r = 0; r < 8; r++) {
            zzr[r] = g_zz[row0 + ty * 8 + r];
            bd[r] = __int_as_float(0x7f800000);
            bk[r] = 0;
        }

        unsigned long long acc[4][8];
        for (int ci = 0; ci < NCH; ci++) {
            const int kc = ci & 7;
            const int nt = ci >> 3;
            if (kc == 0) {
#pragma unroll
                for (int p = 0; p < 4; p++)
#pragma unroll
                    for (int c = 0; c < 8; c++) acc[p][c] = 0ULL;
            }

            if (ci < NCH - 2)      CPWAIT2();  // chunk ci resident
            else if (ci == NCH - 2) CPWAIT1();
            else                    CPWAIT0();
            __syncthreads();                   // visible to all; prior chunk reads done

            // issue chunk ci+3 into buf (ci+3)&3 (nobody reads it this iter)
            if (ci + 3 < NCH) {
                const int ci2 = ci + 3;
                const float* bsrc = g_ebT +
                    ((size_t)(cseg * NTPU + (ci2 >> 3)) * 8 + (ci2 & 7)) * 4096;
                uint32_t bb = sbase + SMB_B0 + (ci2 & 3) * 16384;
#pragma unroll
                for (int i = 0; i < 4; i++) {
                    int f = tid + 256 * i;
                    CPASYNC16(bb + f * 16, bsrc + f * 4);
                }
                CPCOMMIT();
            }

            // ---- compute chunk ci: 32 k x (8 rows x 8 codes) per thread ----
            const float* Ac = At + kc * 4096;
            const float* Bc = smem + (SMB_B0 / 4) + (ci & 3) * 4096;
#pragma unroll 4
            for (int ks = 0; ks < 8; ks++) {
                const int oa0 = (((2 * ty)     ^ ks) << 2);
                const int oa1 = (((2 * ty + 1) ^ ks) << 2);
                const int ob0 = ((tx           ^ ks) << 2);
                const int ob1 = (((16 + tx)    ^ ks) << 2);
                const float* Ak = Ac + ks * 512;
                const float* Bk = Bc + ks * 512;
#pragma unroll
                for (int j = 0; j < 4; j++) {
                    ulonglong2 a01 = *reinterpret_cast<const ulonglong2*>(Ak + j * 128 + oa0);
                    ulonglong2 a23 = *reinterpret_cast<const ulonglong2*>(Ak + j * 128 + oa1);
                    float4 b0 = *reinterpret_cast<const float4*>(Bk + j * 128 + ob0);
                    float4 b1 = *reinterpret_cast<const float4*>(Bk + j * 128 + ob1);

                    unsigned long long d0, d1, d2, d3, d4, d5, d6, d7;
                    DUPB(d0, b0.x); DUPB(d1, b0.y); DUPB(d2, b0.z); DUPB(d3, b0.w);
                    DUPB(d4, b1.x); DUPB(d5, b1.y); DUPB(d6, b1.z); DUPB(d7, b1.w);

                    // a-outer ordering: runs of 8 sharing the A operand (reuse slot)
                    FFMA2(acc[0][0], a01.x, d0); FFMA2(acc[0][1], a01.x, d1);
                    FFMA2(acc[0][2], a01.x, d2); FFMA2(acc[0][3], a01.x, d3);
                    FFMA2(acc[0][4], a01.x, d4); FFMA2(acc[0][5], a01.x, d5);
                    FFMA2(acc[0][6], a01.x, d6); FFMA2(acc[0][7], a01.x, d7);
                    FFMA2(acc[1][0], a01.y, d0); FFMA2(acc[1][1], a01.y, d1);
                    FFMA2(acc[1][2], a01.y, d2); FFMA2(acc[1][3], a01.y, d3);
                    FFMA2(acc[1][4], a01.y, d4); FFMA2(acc[1][5], a01.y, d5);
                    FFMA2(acc[1][6], a01.y, d6); FFMA2(acc[1][7], a01.y, d7);
                    FFMA2(acc[2][0], a23.x, d0); FFMA2(acc[2][1], a23.x, d1);
                    FFMA2(acc[2][2], a23.x, d2); FFMA2(acc[2][3], a23.x, d3);
                    FFMA2(acc[2][4], a23.x, d4); FFMA2(acc[2][5], a23.x, d5);
                    FFMA2(acc[2][6], a23.x, d6); FFMA2(acc[2][7], a23.x, d7);
                    FFMA2(acc[3][0], a23.y, d0); FFMA2(acc[3][1], a23.y, d1);
                    FFMA2(acc[3][2], a23.y, d2); FFMA2(acc[3][3], a23.y, d3);
                    FFMA2(acc[3][4], a23.y, d4); FFMA2(acc[3][5], a23.y, d5);
                    FFMA2(acc[3][6], a23.y, d6); FFMA2(acc[3][7], a23.y, d7);
                }
            }

            // ---- epilogue per n-tile: d = (zz + ee) - 2*s, first-index argmin ----
            if (kc == 7) {
                const int cbase = cseg0 + nt * 128;
#pragma unroll
                for (int g = 0; g < 2; g++) {
#pragma unroll
                    for (int cc = 0; cc < 4; cc++) {
                        const int code = cbase + g * 64 + tx * 4 + cc;
                        const float ee = __ldg(&g_ee[code]);
                        const int ci_ = g * 4 + cc;
#pragma unroll
                        for (int p = 0; p < 4; p++) {
                            float lo, hi;
                            UNPK(lo, hi, acc[p][ci_]);
                            const float dlo = (zzr[2 * p]     + ee) - 2.0f * lo;
                            const float dhi = (zzr[2 * p + 1] + ee) - 2.0f * hi;
                            if (dlo < bd[2 * p])     { bd[2 * p] = dlo;     bk[2 * p] = code; }
                            if (dhi < bd[2 * p + 1]) { bd[2 * p + 1] = dhi; bk[2 * p + 1] = code; }
                        }
                    }
                }
            }
        }

        // ---- reduce across 16 tx lanes, then global atomic merge ----
#pragma unroll
        for (int r = 0; r < 8; r++) {
            float d = bd[r];
            int   k = bk[r];
#pragma unroll
            for (int o = 1; o < 16; o <<= 1) {
                float od = __shfl_xor_sync(0xffffffffu, d, o);
                int   ok = __shfl_xor_sync(0xffffffffu, k, o);
                if (od < d || (od == d && ok < k)) { d = od; k = ok; }
            }
            if (tx == 0) {
                unsigned long long key =
                    ((unsigned long long)__float_as_uint(d) << 32) | (unsigned int)k;
                atomicMin(&g_best[row0 + ty * 8 + r], key);
            }
        }
    }
}

// -------- output gather + straight-through + loss partials --------
__global__ void vq_output_kernel(const float* __restrict__ z, const float* __restrict__ cb,
                                 float* __restrict__ out) {
    const int tid = threadIdx.x;
    const size_t g4 = (size_t)blockIdx.x * 256 + tid;
    const int row = (int)(g4 >> 6);
    const int c4 = (int)(g4 & 63);
    const int idx = (int)(g_best[row] & 0xFFFFFFFFULL);

    const float4 zv = reinterpret_cast<const float4*>(z)[g4];
    const float4 qv = reinterpret_cast<const float4*>(cb)[(size_t)idx * 64 + c4];

    float4 o;
    o.x = zv.x + (qv.x - zv.x);
    o.y = zv.y + (qv.y - zv.y);
    o.z = zv.z + (qv.z - zv.z);
    o.w = zv.w + (qv.w - zv.w);
    reinterpret_cast<float4*>(out)[g4] = o;

    const float dx = zv.x - qv.x, dy = zv.y - qv.y, dz = zv.z - qv.z, dw = zv.w - qv.w;
    float part = dx * dx;
    part = fmaf(dy, dy, part);
    part = fmaf(dz, dz, part);
    part = fmaf(dw, dw, part);

    __shared__ float sp[256];
    sp[tid] = part;
    __syncthreads();
#pragma unroll
    for (int s = 128; s; s >>= 1) {
        if (tid < s) sp[tid] += sp[tid + s];
        __syncthreads();
    }
    if (tid == 0) g_partial[blockIdx.x] = sp[0];
}

// -------- deterministic final loss reduction --------
__global__ void vq_loss_kernel(float* __restrict__ out, int out_size) {
    __shared__ double sm[256];
    const int tid = threadIdx.x;
    double s = 0.0;
    for (int i = tid; i < 8192; i += 256) s += (double)g_partial[i];
    sm[tid] = s;
    __syncthreads();
#pragma unroll
    for (int st = 128; st; st >>= 1) {
        if (tid < st) sm[tid] += sm[tid + st];
        __syncthreads();
    }
    if (tid == 0) {
        const float m = (float)(sm[0] / (double)QSIZE);
        const float vq = 0.25f * m + m;
        for (int i = QSIZE; i < out_size; i++) out[i] = vq;
    }
}

extern "C" void kernel_launch(void* const* d_in, const int* in_sizes, int n_in,
                              void* d_out, int out_size) {
    const float* z  = (const float*)d_in[0];
    const float* cb = (const float*)d_in[1];
    if (n_in >= 2 && in_sizes[0] == KCODES * DD && in_sizes[1] == NROWS * DD) {
        const float* t = z; z = cb; cb = t;
    }
    float* out = (float*)d_out;

    cudaFuncSetAttribute(vq_argmin_kernel,
                         cudaFuncAttributeMaxDynamicSharedMemorySize, SM_TOTAL);

    float* zz_ptr; cudaGetSymbolAddress((void**)&zz_ptr, g_zz);
    float* ee_ptr; cudaGetSymbolAddress((void**)&ee_ptr, g_ee);

    vq_init_kernel<<<NROWS / 256, 256>>>();
    vq_norms_kernel<<<(NROWS * 32) / 256, 256>>>(z, zz_ptr, NROWS);
    vq_norms_kernel<<<(KCODES * 32) / 256, 256>>>(cb, ee_ptr, KCODES);
    vq_prep_z<<<512, 256>>>(z);
    vq_prep_cb<<<512, 256>>>(cb);
    vq_argmin_kernel<<<148, 256, SM_TOTAL>>>();
    vq_output_kernel<<<QSIZE / 1024, 256>>>(z, cb, out);
    vq_loss_kernel<<<1, 256>>>(out, out_size);
}